// round 16
// baseline (speedup 1.0000x reference)
#include <cuda_runtime.h>
#include <cuda_bf16.h>
#include <cstdint>
#include <cstddef>

#define H 16
#define DMODEL 1024
#define DK 64
#define BB 2
#define SS 2048
#define M_ROWS (BB*SS)   // 4096

#define ACT_SZ  ((size_t)M_ROWS*DMODEL)
#define W_SZ    ((size_t)DMODEL*DMODEL)
#define HEAD_SZ ((size_t)BB*H*SS*DK)

typedef unsigned long long u64;

// Scratch (device globals — no allocation allowed)
__device__ unsigned int g_mbits[(size_t)BB*SS*(SS/32)];
// slot 0=Q, 1=K, 2=V head-major [b,h,s,dk] bf16 hi/lo
__device__ __nv_bfloat16 g_headh[3*HEAD_SZ];
__device__ __nv_bfloat16 g_headl[3*HEAD_SZ];
// slot 0..2 = q,k,v activations; slot 0 reused for attention output
__device__ __nv_bfloat16 g_acth[3*ACT_SZ];
__device__ __nv_bfloat16 g_actl[3*ACT_SZ];
// slot 0..3 = Wq,Wk,Wv,Wo
__device__ __nv_bfloat16 g_wh[4*W_SZ];
__device__ __nv_bfloat16 g_wl[4*W_SZ];

#define QSCALE 0.18033688011112042f   /* (1/8) * log2(e) */
#define MASKVAL (-14427.0f)           /* -10000 * log2(e)  */

// ---------------------------------------------------------------------------
// helpers
// ---------------------------------------------------------------------------
__device__ __forceinline__ u64 pack2(float x, float y) {
    u64 d; asm("mov.b64 %0, {%1, %2};" : "=l"(d) : "f"(x), "f"(y)); return d;
}
__device__ __forceinline__ float ex2(float x) {
    float y; asm("ex2.approx.f32 %0, %1;" : "=f"(y) : "f"(x)); return y;
}
__device__ __forceinline__ uint32_t smem_u32(const void* p) {
    uint32_t a;
    asm("{ .reg .u64 t; cvta.to.shared.u64 t, %1; cvt.u32.u64 %0, t; }" : "=r"(a) : "l"(p));
    return a;
}
__device__ __forceinline__ void split_pair(float x, float y, uint32_t& hi, uint32_t& lo) {
    __nv_bfloat162 hp = __floats2bfloat162_rn(x, y);
    float rx = x - __bfloat162float(hp.x);
    float ry = y - __bfloat162float(hp.y);
    __nv_bfloat162 lp2 = __floats2bfloat162_rn(rx, ry);
    hi = *(uint32_t*)&hp; lo = *(uint32_t*)&lp2;
}

#define LDSM4(r, a) \
    asm volatile("ldmatrix.sync.aligned.m8n8.x4.shared.b16 {%0,%1,%2,%3}, [%4];" \
        : "=r"((r)[0]), "=r"((r)[1]), "=r"((r)[2]), "=r"((r)[3]) : "r"(a))
#define LDSM4T(r, a) \
    asm volatile("ldmatrix.sync.aligned.m8n8.x4.trans.shared.b16 {%0,%1,%2,%3}, [%4];" \
        : "=r"((r)[0]), "=r"((r)[1]), "=r"((r)[2]), "=r"((r)[3]) : "r"(a))
#define MMA16816(d, a, b) \
    asm volatile("mma.sync.aligned.m16n8k16.row.col.f32.bf16.bf16.f32 " \
        "{%0,%1,%2,%3}, {%4,%5,%6,%7}, {%8,%9}, {%0,%1,%2,%3};" \
        : "+f"((d)[0]), "+f"((d)[1]), "+f"((d)[2]), "+f"((d)[3]) \
        : "r"((a)[0]), "r"((a)[1]), "r"((a)[2]), "r"((a)[3]), "r"((b)[0]), "r"((b)[1]))
#define CP_ASYNC16(dst, src) \
    asm volatile("cp.async.ca.shared.global [%0], [%1], 16;" :: "r"(dst), "l"(src))
#define CP_COMMIT() asm volatile("cp.async.commit_group;")
#define CP_WAIT(n)  asm volatile("cp.async.wait_group %0;" :: "n"(n))

// ---------------------------------------------------------------------------
// fused fp32 -> bf16 hi/lo splits
// ---------------------------------------------------------------------------
__global__ __launch_bounds__(256)
void conv_split_act(const float* __restrict__ s0, const float* __restrict__ s1,
                    const float* __restrict__ s2)
{
    const float* src = (blockIdx.y == 0) ? s0 : (blockIdx.y == 1) ? s1 : s2;
    __nv_bfloat16* hi = g_acth + (size_t)blockIdx.y * ACT_SZ;
    __nv_bfloat16* lo = g_actl + (size_t)blockIdx.y * ACT_SZ;
    size_t i = ((size_t)blockIdx.x * 256 + threadIdx.x) * 4;
    float4 v = *(const float4*)&src[i];
    uint32_t h0, l0, h1, l1;
    split_pair(v.x, v.y, h0, l0);
    split_pair(v.z, v.w, h1, l1);
    *(uint2*)&hi[i] = make_uint2(h0, h1);
    *(uint2*)&lo[i] = make_uint2(l0, l1);
}

__global__ __launch_bounds__(256)
void conv_split_w(const float* __restrict__ s0, const float* __restrict__ s1,
                  const float* __restrict__ s2, const float* __restrict__ s3)
{
    const float* src = (blockIdx.y == 0) ? s0 : (blockIdx.y == 1) ? s1 :
                       (blockIdx.y == 2) ? s2 : s3;
    __nv_bfloat16* hi = g_wh + (size_t)blockIdx.y * W_SZ;
    __nv_bfloat16* lo = g_wl + (size_t)blockIdx.y * W_SZ;
    size_t i = ((size_t)blockIdx.x * 256 + threadIdx.x) * 4;
    float4 v = *(const float4*)&src[i];
    uint32_t h0, l0, h1, l1;
    split_pair(v.x, v.y, h0, l0);
    split_pair(v.z, v.w, h1, l1);
    *(uint2*)&hi[i] = make_uint2(h0, h1);
    *(uint2*)&lo[i] = make_uint2(l0, l1);
}

// ---------------------------------------------------------------------------
// Mask bit-pack
// ---------------------------------------------------------------------------
__global__ __launch_bounds__(256)
void pack_mask(const int* __restrict__ m)
{
    size_t i = (size_t)blockIdx.x * 256 + threadIdx.x;
    unsigned bit = (m[i] != 0) ? 1u : 0u;
    unsigned w = __ballot_sync(0xffffffff, bit);
    if ((threadIdx.x & 31) == 0) g_mbits[i >> 5] = w;
}

// ---------------------------------------------------------------------------
// bf16x3 HMMA GEMM core (3-stage cp.async pipeline) — unchanged from R13.
// ---------------------------------------------------------------------------
#define NST 3
#define NCHUNKS (DMODEL / 16)   // 64

__device__ __forceinline__ uint32_t tile_off(int s, int t, int row, int ch) {
    return (uint32_t)(((((s * 4 + t) * 128 + row) << 4) +
                       ((ch ^ ((row >> 2) & 1)) << 3)) << 1);
}

template<int LAYOUT>
__device__ __forceinline__ void gemm_body(
    const __nv_bfloat16* __restrict__ Ah, const __nv_bfloat16* __restrict__ Al,
    const __nv_bfloat16* __restrict__ Wh, const __nv_bfloat16* __restrict__ Wl,
    const float* __restrict__ bias, float* __restrict__ C,
    __nv_bfloat16* __restrict__ Chi, __nv_bfloat16* __restrict__ Clo,
    float scale, __nv_bfloat16* sm)
{
    const int tid  = threadIdx.x;
    const int lane = tid & 31;
    const int w    = tid >> 5;
    const int wm   = (w >> 2) * 64;
    const int wn   = (w & 3) * 32;
    const int n0 = blockIdx.x * 128;
    const int m0 = blockIdx.y * 128;
    const uint32_t sb = smem_u32(sm);

    const __nv_bfloat16* srcs[4] = {
        Ah + (size_t)m0 * DMODEL, Al + (size_t)m0 * DMODEL,
        Wh + (size_t)n0 * DMODEL, Wl + (size_t)n0 * DMODEL };

    const int lrow = tid >> 1;
    const int lch  = tid & 1;
    const size_t lgof = (size_t)lrow * DMODEL + lch * 8;

    float acc[4][4][4];
    #pragma unroll
    for (int mt = 0; mt < 4; mt++)
        #pragma unroll
        for (int nt = 0; nt < 4; nt++)
            #pragma unroll
            for (int e = 0; e < 4; e++) acc[mt][nt][e] = 0.f;

    #pragma unroll
    for (int c = 0; c < NST - 1; c++) {
        #pragma unroll
        for (int t = 0; t < 4; t++)
            CP_ASYNC16(sb + tile_off(c, t, lrow, lch), srcs[t] + lgof + c * 16);
        CP_COMMIT();
    }

    const int a_row = lane & 15;
    const int a_ch  = lane >> 4;

    for (int c = 0; c < NCHUNKS; c++) {
        const int s = c % NST;
        CP_WAIT(1);
        __syncthreads();

        const int cn = c + NST - 1;
        if (cn < NCHUNKS) {
            #pragma unroll
            for (int t = 0; t < 4; t++)
                CP_ASYNC16(sb + tile_off(cn % NST, t, lrow, lch), srcs[t] + lgof + cn * 16);
        }
        CP_COMMIT();

        uint32_t ah[4][4], al[4][4];
        #pragma unroll
        for (int mt = 0; mt < 4; mt++) {
            LDSM4(ah[mt], sb + tile_off(s, 0, wm + mt * 16 + a_row, a_ch));
            LDSM4(al[mt], sb + tile_off(s, 1, wm + mt * 16 + a_row, a_ch));
        }
        uint32_t b4h[2][4], b4l[2][4];
        #pragma unroll
        for (int p = 0; p < 2; p++) {
            LDSM4(b4h[p], sb + tile_off(s, 2, wn + p * 16 + a_row, a_ch));
            LDSM4(b4l[p], sb + tile_off(s, 3, wn + p * 16 + a_row, a_ch));
        }
        uint32_t bh[4][2], bl[4][2];
        #pragma unroll
        for (int p = 0; p < 2; p++) {
            bh[2*p][0]   = b4h[p][0]; bh[2*p][1]   = b4h[p][2];
            bh[2*p+1][0] = b4h[p][1]; bh[2*p+1][1] = b4h[p][3];
            bl[2*p][0]   = b4l[p][0]; bl[2*p][1]   = b4l[p][2];
            bl[2*p+1][0] = b4l[p][1]; bl[2*p+1][1] = b4l[p][3];
        }
        #pragma unroll
        for (int mt = 0; mt < 4; mt++)
            #pragma unroll
            for (int nt = 0; nt < 4; nt++) {
                MMA16816(acc[mt][nt], ah[mt], bh[nt]);
                MMA16816(acc[mt][nt], ah[mt], bl[nt]);
                MMA16816(acc[mt][nt], al[mt], bh[nt]);
            }
    }

    const int er = lane >> 2;
    const int ec = (lane & 3) * 2;
    #pragma unroll
    for (int mt = 0; mt < 4; mt++) {
        #pragma unroll
        for (int half = 0; half < 2; half++) {
            int m = m0 + wm + mt * 16 + er + half * 8;
            #pragma unroll
            for (int nt = 0; nt < 4; nt++) {
                int n = n0 + wn + nt * 8 + ec;
                float f0 = (acc[mt][nt][half * 2 + 0] + __ldg(&bias[n]))     * scale;
                float f1 = (acc[mt][nt][half * 2 + 1] + __ldg(&bias[n + 1])) * scale;
                if (LAYOUT == 0) {
                    *(u64*)&C[(size_t)m * DMODEL + n] = pack2(f0, f1);
                } else {
                    int b  = m >> 11;
                    int sq = m & (SS - 1);
                    int hh = n >> 6;
                    int dk = n & (DK - 1);
                    size_t o = ((((size_t)b * H + hh) * SS + sq) * DK) + dk;
                    uint32_t hi, lo;
                    split_pair(f0, f1, hi, lo);
                    *(uint32_t*)&Chi[o] = hi;
                    *(uint32_t*)&Clo[o] = lo;
                }
            }
        }
    }
}

__global__ __launch_bounds__(256, 2)
void gemm_qkv(const float* __restrict__ bq, const float* __restrict__ bk,
              const float* __restrict__ bv)
{
    __shared__ __align__(16) __nv_bfloat16 sm[NST * 4 * 128 * 16];
    const size_t z = blockIdx.z;
    const float* bias = (z == 0) ? bq : (z == 1) ? bk : bv;
    const float scale = (z == 0) ? QSCALE : 1.0f;
    gemm_body<1>(g_acth + z * ACT_SZ, g_actl + z * ACT_SZ,
                 g_wh + z * W_SZ, g_wl + z * W_SZ,
                 bias, nullptr,
                 g_headh + z * HEAD_SZ, g_headl + z * HEAD_SZ,
                 scale, sm);
}

__global__ __launch_bounds__(256, 2)
void gemm_out(const float* __restrict__ bo, float* __restrict__ C)
{
    __shared__ __align__(16) __nv_bfloat16 sm[NST * 4 * 128 * 16];
    gemm_body<0>(g_acth, g_actl, g_wh + 3 * W_SZ, g_wl + 3 * W_SZ,
                 bo, C, nullptr, nullptr, 1.0f, sm);
}

// ---------------------------------------------------------------------------
// HMMA flash attention (bf16x3). 128 threads, 64 q-rows/block (R13 shape) +
// mask slab preloaded to smem (transposed: m_sm[word][row]) to kill the
// per-iteration scattered mask LDG on the softmax critical path.
// Smem: 32KB KV + 16KB mask = exactly 48KB static.
// ---------------------------------------------------------------------------
__device__ __forceinline__ uint32_t kv_off(int s, int t, int row, int ch) {
    return (uint32_t)((((s * 4 + t) * 32 + row) * 128) + ((ch ^ (row & 7)) * 16));
}

__global__ __launch_bounds__(128)
void attn_mma()
{
    __shared__ __align__(16) char sKV[32768];       // 2 stages x 4 tiles x 4KB
    __shared__ unsigned m_sm[64 * 64];              // [word][row] = 16KB

    const int tid  = threadIdx.x;
    const int lane = tid & 31;
    const int w    = tid >> 5;
    const int wq   = w * 16;
    const int q0 = blockIdx.x * 64;
    const int h  = blockIdx.y;
    const int bz = blockIdx.z;
    const uint32_t sb = smem_u32(sKV);

    const size_t hb = ((size_t)bz * H + h) * SS;
    const __nv_bfloat16* gqh = g_headh + (hb + q0) * DK;
    const __nv_bfloat16* gql = g_headl + (hb + q0) * DK;
    const __nv_bfloat16* kvsrc[4] = {
        g_headh + HEAD_SZ + hb * DK, g_headl + HEAD_SZ + hb * DK,
        g_headh + 2 * HEAD_SZ + hb * DK, g_headl + 2 * HEAD_SZ + hb * DK };

    // ---- preload mask slab: rows q0..q0+63, all 64 words, transposed ----
    {
        const unsigned* msrc = g_mbits + ((size_t)bz * SS + q0) * (SS / 32);
        #pragma unroll
        for (int i = 0; i < 8; i++) {
            int idx = tid + i * 128;            // 0..1023 uint4 chunks
            int row = idx >> 4;                 // 0..63
            int w4  = (idx & 15) * 4;           // word group
            uint4 mv = *(const uint4*)(msrc + (size_t)row * (SS / 32) + w4);
            m_sm[(w4 + 0) * 64 + row] = mv.x;
            m_sm[(w4 + 1) * 64 + row] = mv.y;
            m_sm[(w4 + 2) * 64 + row] = mv.z;
            m_sm[(w4 + 3) * 64 + row] = mv.w;
        }
    }

    // ---- stage Q (64 x 64 hi+lo) through stage-0 smem, swizzled ----
    #pragma unroll
    for (int i = 0; i < 8; i++) {
        int idx = tid + i * 128;
        int arr = idx >> 9;
        int rem = idx & 511;
        int row = rem >> 3, ch = rem & 7;
        const __nv_bfloat16* src = (arr ? gql : gqh) + (size_t)row * DK + ch * 8;
        *(uint4*)(sKV + kv_off(0, arr * 2 + (row >> 5), row & 31, ch)) = *(const uint4*)src;
    }
    __syncthreads();

    uint32_t qfh[4][4], qfl[4][4];
    {
        const int a_row = lane & 15, a_ch = lane >> 4;
        const int r = wq + a_row, lr = r & 31, ts = r >> 5;
        #pragma unroll
        for (int ks = 0; ks < 4; ks++) {
            LDSM4(qfh[ks], sb + kv_off(0, ts, lr, ks * 2 + a_ch));
            LDSM4(qfl[ks], sb + kv_off(0, 2 + ts, lr, ks * 2 + a_ch));
        }
    }
    __syncthreads();

    float acc[8][4];
    #pragma unroll
    for (int nt = 0; nt < 8; nt++)
        #pragma unroll
        for (int e = 0; e < 4; e++) acc[nt][e] = 0.f;
    float mrun0 = -1e30f, mrun1 = -1e30f;
    float lp0 = 0.f, lp1 = 0.f;

    const int er = lane >> 2, ec = (lane & 3) * 2;
    const int mr0 = wq + er;          // local q row for mask
    const int mr1 = mr0 + 8;

    // ---- prologue: issue K/V tile 0 ----
    #pragma unroll
    for (int i = 0; i < 8; i++) {
        int idx = tid + i * 128;
        int t = idx >> 8, rem = idx & 255, row = rem >> 3, ch = rem & 7;
        CP_ASYNC16(sb + kv_off(0, t, row, ch), kvsrc[t] + (size_t)row * DK + ch * 8);
    }
    CP_COMMIT();

    for (int it = 0; it < SS / 32; it++) {
        const int st = it & 1;
        CP_WAIT(0);
        __syncthreads();

        if (it + 1 < SS / 32) {
            const int k0n = (it + 1) * 32;
            #pragma unroll
            for (int i = 0; i < 8; i++) {
                int idx = tid + i * 128;
                int t = idx >> 8, rem = idx & 255, row = rem >> 3, ch = rem & 7;
                CP_ASYNC16(sb + kv_off(st ^ 1, t, row, ch),
                           kvsrc[t] + (size_t)(k0n + row) * DK + ch * 8);
            }
        }
        CP_COMMIT();

        float sc[4][4];
        #pragma unroll
        for (int nt = 0; nt < 4; nt++)
            #pragma unroll
            for (int e = 0; e < 4; e++) sc[nt][e] = 0.f;

        #pragma unroll
        for (int ks = 0; ks < 4; ks++) {
            uint32_t kc0h[4], kc1h[4], kc0l[4], kc1l[4];
            LDSM4(kc0h, sb + kv_off(st, 0, lane, ks * 2));
            LDSM4(kc1h, sb + kv_off(st, 0, lane, ks * 2 + 1));
            LDSM4(kc0l, sb + kv_off(st, 1, lane, ks * 2));
            LDSM4(kc1l, sb + kv_off(st, 1, lane, ks * 2 + 1));
            #pragma unroll
            for (int nt = 0; nt < 4; nt++) {
                uint32_t bh[2] = { kc0h[nt], kc1h[nt] };
                uint32_t bl[2] = { kc0l[nt], kc1l[nt] };
                MMA16816(sc[nt], qfh[ks], bh);
                MMA16816(sc[nt], qfh[ks], bl);
                MMA16816(sc[nt], qfl[ks], bh);
            }
        }

        // --- mask (from smem, conflict-free broadcast) + online softmax ---
        unsigned mw0 = m_sm[it * 64 + mr0];
        unsigned mw1 = m_sm[it * 64 + mr1];
        #pragma unroll
        for (int nt = 0; nt < 4; nt++) {
            int j0 = nt * 8 + ec;
            if (!((mw0 >> j0) & 1u))       sc[nt][0] = MASKVAL;
            if (!((mw0 >> (j0 + 1)) & 1u)) sc[nt][1] = MASKVAL;
            if (!((mw1 >> j0) & 1u))       sc[nt][2] = MASKVAL;
            if (!((mw1 >> (j0 + 1)) & 1u)) sc[nt][3] = MASKVAL;
        }
        float m0 = mrun0, m1 = mrun1;
        #pragma unroll
        for (int nt = 0; nt < 4; nt++) {
            m0 = fmaxf(m0, fmaxf(sc[nt][0], sc[nt][1]));
            m1 = fmaxf(m1, fmaxf(sc[nt][2], sc[nt][3]));
        }
        m0 = fmaxf(m0, __shfl_xor_sync(0xffffffff, m0, 1));
        m0 = fmaxf(m0, __shfl_xor_sync(0xffffffff, m0, 2));
        m1 = fmaxf(m1, __shfl_xor_sync(0xffffffff, m1, 1));
        m1 = fmaxf(m1, __shfl_xor_sync(0xffffffff, m1, 2));
        float al0 = ex2(mrun0 - m0);
        float al1 = ex2(mrun1 - m1);
        mrun0 = m0; mrun1 = m1;
        lp0 *= al0; lp1 *= al1;
        #pragma unroll
        for (int nt = 0; nt < 8; nt++) {
            acc[nt][0] *= al0; acc[nt][1] *= al0;
            acc[nt][2] *= al1; acc[nt][3] *= al1;
        }
        float s0 = 0.f, s1 = 0.f;
        #pragma unroll
        for (int nt = 0; nt < 4; nt++) {
            sc[nt][0] = ex2(sc[nt][0] - m0); s0 += sc[nt][0];
            sc[nt][1] = ex2(sc[nt][1] - m0); s0 += sc[nt][1];
            sc[nt][2] = ex2(sc[nt][2] - m1); s1 += sc[nt][2];
            sc[nt][3] = ex2(sc[nt][3] - m1); s1 += sc[nt][3];
        }
        lp0 += s0; lp1 += s1;

        // --- PV: P fragments from score registers, V via ldmatrix.x4.trans ---
        #pragma unroll
        for (int t2 = 0; t2 < 2; t2++) {
            uint32_t ph[4], pl[4];
            split_pair(sc[2*t2][0],   sc[2*t2][1],   ph[0], pl[0]);
            split_pair(sc[2*t2][2],   sc[2*t2][3],   ph[1], pl[1]);
            split_pair(sc[2*t2+1][0], sc[2*t2+1][1], ph[2], pl[2]);
            split_pair(sc[2*t2+1][2], sc[2*t2+1][3], ph[3], pl[3]);
            const int vrow = t2 * 16 + (lane & 15);
            const int vch  = lane >> 4;
            #pragma unroll
            for (int p = 0; p < 4; p++) {
                uint32_t v4h[4], v4l[4];
                LDSM4T(v4h, sb + kv_off(st, 2, vrow, 2 * p + vch));
                LDSM4T(v4l, sb + kv_off(st, 3, vrow, 2 * p + vch));
                uint32_t vh0[2] = { v4h[0], v4h[1] }, vl0[2] = { v4l[0], v4l[1] };
                uint32_t vh1[2] = { v4h[2], v4h[3] }, vl1[2] = { v4l[2], v4l[3] };
                MMA16816(acc[2*p],   ph, vh0);
                MMA16816(acc[2*p],   ph, vl0);
                MMA16816(acc[2*p],   pl, vh0);
                MMA16816(acc[2*p+1], ph, vh1);
                MMA16816(acc[2*p+1], ph, vl1);
                MMA16816(acc[2*p+1], pl, vh1);
            }
        }
    }

    lp0 += __shfl_xor_sync(0xffffffff, lp0, 1);
    lp0 += __shfl_xor_sync(0xffffffff, lp0, 2);
    lp1 += __shfl_xor_sync(0xffffffff, lp1, 1);
    lp1 += __shfl_xor_sync(0xffffffff, lp1, 2);
    float inv0 = 1.0f / lp0;
    float inv1 = 1.0f / lp1;

    size_t ro0 = ((size_t)bz * SS + q0 + wq + er) * DMODEL + (size_t)h * DK;
    size_t ro1 = ro0 + 8 * DMODEL;
    #pragma unroll
    for (int nt = 0; nt < 8; nt++) {
        int c = nt * 8 + ec;
        uint32_t hi, lo;
        split_pair(acc[nt][0] * inv0, acc[nt][1] * inv0, hi, lo);
        *(uint32_t*)&g_acth[ro0 + c] = hi;
        *(uint32_t*)&g_actl[ro0 + c] = lo;
        split_pair(acc[nt][2] * inv1, acc[nt][3] * inv1, hi, lo);
        *(uint32_t*)&g_acth[ro1 + c] = hi;
        *(uint32_t*)&g_actl[ro1 + c] = lo;
    }
}

// ---------------------------------------------------------------------------
extern "C" void kernel_launch(void* const* d_in, const int* in_sizes, int n_in,
                              void* d_out, int out_size)
{
    const float* q    = (const float*)d_in[0];
    const float* k    = (const float*)d_in[1];
    const float* v    = (const float*)d_in[2];
    const int*   mask = (const int*)  d_in[3];
    const float* Wq   = (const float*)d_in[4];
    const float* bq   = (const float*)d_in[5];
    const float* Wk   = (const float*)d_in[6];
    const float* bk   = (const float*)d_in[7];
    const float* Wv   = (const float*)d_in[8];
    const float* bv   = (const float*)d_in[9];
    const float* Wo   = (const float*)d_in[10];
    const float* bo   = (const float*)d_in[11];
    float* out = (float*)d_out;

    const int ACT_BLKS = (M_ROWS * DMODEL) / (256 * 4);   // 4096
    const int W_BLKS   = (DMODEL * DMODEL) / (256 * 4);   // 1024
    dim3 gq3(DMODEL / 128, M_ROWS / 128, 3);               // (8, 32, 3)
    dim3 go(DMODEL / 128, M_ROWS / 128);                   // (8, 32)

    pack_mask<<<(size_t)BB * SS * SS / 256, 256>>>(mask);
    conv_split_w<<<dim3(W_BLKS, 4), 256>>>(Wq, Wk, Wv, Wo);
    conv_split_act<<<dim3(ACT_BLKS, 3), 256>>>(q, k, v);

    gemm_qkv<<<gq3, 256>>>(bq, bk, bv);

    attn_mma<<<dim3(SS / 64, H, BB), 128>>>();

    gemm_out<<<go, 256>>>(bo, out);
}

// round 17
// speedup vs baseline: 1.2416x; 1.2416x over previous
#include <cuda_runtime.h>
#include <cuda_bf16.h>
#include <cuda_fp16.h>
#include <cstdint>
#include <cstddef>

#define H 16
#define DMODEL 1024
#define DK 64
#define BB 2
#define SS 2048
#define M_ROWS (BB*SS)   // 4096

#define ACT_SZ  ((size_t)M_ROWS*DMODEL)
#define W_SZ    ((size_t)DMODEL*DMODEL)
#define HEAD_SZ ((size_t)BB*H*SS*DK)

typedef unsigned long long u64;

// Scratch (device globals — no allocation allowed)
__device__ unsigned int g_mbits[(size_t)BB*SS*(SS/32)];
// slot 0=Q, 1=K, 2=V head-major [b,h,s,dk] bf16 hi/lo (attention operands)
__device__ __nv_bfloat16 g_headh[3*HEAD_SZ];
__device__ __nv_bfloat16 g_headl[3*HEAD_SZ];
// fp16 activations: slot 0..2 = q,k,v; slot 0 reused for attention output
__device__ __half g_act[3*ACT_SZ];
// fp16 weight hi/lo: slot 0..3 = Wq,Wk,Wv,Wo
__device__ __half g_wh[4*W_SZ];
__device__ __half g_wl[4*W_SZ];

#define QSCALE 0.18033688011112042f   /* (1/8) * log2(e) */
#define MASKVAL (-14427.0f)           /* -10000 * log2(e)  */

// ---------------------------------------------------------------------------
// helpers
// ---------------------------------------------------------------------------
__device__ __forceinline__ u64 pack2(float x, float y) {
    u64 d; asm("mov.b64 %0, {%1, %2};" : "=l"(d) : "f"(x), "f"(y)); return d;
}
__device__ __forceinline__ float ex2(float x) {
    float y; asm("ex2.approx.f32 %0, %1;" : "=f"(y) : "f"(x)); return y;
}
__device__ __forceinline__ uint32_t smem_u32(const void* p) {
    uint32_t a;
    asm("{ .reg .u64 t; cvta.to.shared.u64 t, %1; cvt.u32.u64 %0, t; }" : "=r"(a) : "l"(p));
    return a;
}
// bf16 hi/lo split (attention path, unchanged numerics)
__device__ __forceinline__ void split_pair(float x, float y, uint32_t& hi, uint32_t& lo) {
    __nv_bfloat162 hp = __floats2bfloat162_rn(x, y);
    float rx = x - __bfloat162float(hp.x);
    float ry = y - __bfloat162float(hp.y);
    __nv_bfloat162 lp2 = __floats2bfloat162_rn(rx, ry);
    hi = *(uint32_t*)&hp; lo = *(uint32_t*)&lp2;
}
// fp16 hi/lo split (weights)
__device__ __forceinline__ void split_pair_h(float x, float y, uint32_t& hi, uint32_t& lo) {
    __half2 hp = __floats2half2_rn(x, y);
    float rx = x - __half2float(hp.x);
    float ry = y - __half2float(hp.y);
    __half2 lp = __floats2half2_rn(rx, ry);
    hi = *(uint32_t*)&hp; lo = *(uint32_t*)&lp;
}

#define LDSM4(r, a) \
    asm volatile("ldmatrix.sync.aligned.m8n8.x4.shared.b16 {%0,%1,%2,%3}, [%4];" \
        : "=r"((r)[0]), "=r"((r)[1]), "=r"((r)[2]), "=r"((r)[3]) : "r"(a))
#define LDSM4T(r, a) \
    asm volatile("ldmatrix.sync.aligned.m8n8.x4.trans.shared.b16 {%0,%1,%2,%3}, [%4];" \
        : "=r"((r)[0]), "=r"((r)[1]), "=r"((r)[2]), "=r"((r)[3]) : "r"(a))
// bf16 MMA (attention)
#define MMA16816(d, a, b) \
    asm volatile("mma.sync.aligned.m16n8k16.row.col.f32.bf16.bf16.f32 " \
        "{%0,%1,%2,%3}, {%4,%5,%6,%7}, {%8,%9}, {%0,%1,%2,%3};" \
        : "+f"((d)[0]), "+f"((d)[1]), "+f"((d)[2]), "+f"((d)[3]) \
        : "r"((a)[0]), "r"((a)[1]), "r"((a)[2]), "r"((a)[3]), "r"((b)[0]), "r"((b)[1]))
// fp16 MMA (projection GEMMs)
#define MMA16816H(d, a, b) \
    asm volatile("mma.sync.aligned.m16n8k16.row.col.f32.f16.f16.f32 " \
        "{%0,%1,%2,%3}, {%4,%5,%6,%7}, {%8,%9}, {%0,%1,%2,%3};" \
        : "+f"((d)[0]), "+f"((d)[1]), "+f"((d)[2]), "+f"((d)[3]) \
        : "r"((a)[0]), "r"((a)[1]), "r"((a)[2]), "r"((a)[3]), "r"((b)[0]), "r"((b)[1]))
#define CP_ASYNC16(dst, src) \
    asm volatile("cp.async.ca.shared.global [%0], [%1], 16;" :: "r"(dst), "l"(src))
#define CP_COMMIT() asm volatile("cp.async.commit_group;")
#define CP_WAIT(n)  asm volatile("cp.async.wait_group %0;" :: "n"(n))

// ---------------------------------------------------------------------------
// fp32 -> fp16 convert (activations, single array)
// ---------------------------------------------------------------------------
__global__ __launch_bounds__(256)
void conv_act(const float* __restrict__ s0, const float* __restrict__ s1,
              const float* __restrict__ s2)
{
    const float* src = (blockIdx.y == 0) ? s0 : (blockIdx.y == 1) ? s1 : s2;
    __half* dst = g_act + (size_t)blockIdx.y * ACT_SZ;
    size_t i = ((size_t)blockIdx.x * 256 + threadIdx.x) * 4;
    float4 v = *(const float4*)&src[i];
    __half2 a = __floats2half2_rn(v.x, v.y);
    __half2 b = __floats2half2_rn(v.z, v.w);
    *(uint2*)&dst[i] = make_uint2(*(uint32_t*)&a, *(uint32_t*)&b);
}

// fp32 -> fp16 hi/lo split (weights)
__global__ __launch_bounds__(256)
void conv_split_w(const float* __restrict__ s0, const float* __restrict__ s1,
                  const float* __restrict__ s2, const float* __restrict__ s3)
{
    const float* src = (blockIdx.y == 0) ? s0 : (blockIdx.y == 1) ? s1 :
                       (blockIdx.y == 2) ? s2 : s3;
    __half* hi = g_wh + (size_t)blockIdx.y * W_SZ;
    __half* lo = g_wl + (size_t)blockIdx.y * W_SZ;
    size_t i = ((size_t)blockIdx.x * 256 + threadIdx.x) * 4;
    float4 v = *(const float4*)&src[i];
    uint32_t h0, l0, h1, l1;
    split_pair_h(v.x, v.y, h0, l0);
    split_pair_h(v.z, v.w, h1, l1);
    *(uint2*)&hi[i] = make_uint2(h0, h1);
    *(uint2*)&lo[i] = make_uint2(l0, l1);
}

// ---------------------------------------------------------------------------
// Mask bit-pack
// ---------------------------------------------------------------------------
__global__ __launch_bounds__(256)
void pack_mask(const int* __restrict__ m)
{
    size_t i = (size_t)blockIdx.x * 256 + threadIdx.x;
    unsigned bit = (m[i] != 0) ? 1u : 0u;
    unsigned w = __ballot_sync(0xffffffff, bit);
    if ((threadIdx.x & 31) == 0) g_mbits[i >> 5] = w;
}

// ---------------------------------------------------------------------------
// fp16 2-term HMMA GEMM: C = A @ (Wh+Wl)^T + bias,  A single fp16.
// 4-stage cp.async pipeline, 3 tiles/stage (A, Wh, Wl) x 4KB = 48KB static.
// Block 128x128, K-chunk 16 (64 chunks), 256 threads = 8 warps (2m x 4n).
// ---------------------------------------------------------------------------
#define NST 4
#define NCHUNKS (DMODEL / 16)   // 64

__device__ __forceinline__ uint32_t tile_off(int s, int t, int row, int ch) {
    return (uint32_t)(((((s * 3 + t) * 128 + row) << 4) +
                       ((ch ^ ((row >> 2) & 1)) << 3)) << 1);
}

template<int LAYOUT>
__device__ __forceinline__ void gemm_body(
    const __half* __restrict__ A,
    const __half* __restrict__ Wh, const __half* __restrict__ Wl,
    const float* __restrict__ bias, float* __restrict__ C,
    __nv_bfloat16* __restrict__ Chi, __nv_bfloat16* __restrict__ Clo,
    float scale, __half* sm)
{
    const int tid  = threadIdx.x;
    const int lane = tid & 31;
    const int w    = tid >> 5;
    const int wm   = (w >> 2) * 64;
    const int wn   = (w & 3) * 32;
    const int n0 = blockIdx.x * 128;
    const int m0 = blockIdx.y * 128;
    const uint32_t sb = smem_u32(sm);

    const __half* srcs[3] = {
        A + (size_t)m0 * DMODEL,
        Wh + (size_t)n0 * DMODEL, Wl + (size_t)n0 * DMODEL };

    const int lrow = tid >> 1;
    const int lch  = tid & 1;
    const size_t lgof = (size_t)lrow * DMODEL + lch * 8;

    float acc[4][4][4];
    #pragma unroll
    for (int mt = 0; mt < 4; mt++)
        #pragma unroll
        for (int nt = 0; nt < 4; nt++)
            #pragma unroll
            for (int e = 0; e < 4; e++) acc[mt][nt][e] = 0.f;

    #pragma unroll
    for (int c = 0; c < NST - 1; c++) {
        #pragma unroll
        for (int t = 0; t < 3; t++)
            CP_ASYNC16(sb + tile_off(c, t, lrow, lch), srcs[t] + lgof + c * 16);
        CP_COMMIT();
    }

    const int a_row = lane & 15;
    const int a_ch  = lane >> 4;

    for (int c = 0; c < NCHUNKS; c++) {
        const int s = c & (NST - 1);
        CP_WAIT(2);
        __syncthreads();

        const int cn = c + NST - 1;
        if (cn < NCHUNKS) {
            #pragma unroll
            for (int t = 0; t < 3; t++)
                CP_ASYNC16(sb + tile_off(cn & (NST - 1), t, lrow, lch),
                           srcs[t] + lgof + cn * 16);
        }
        CP_COMMIT();

        uint32_t ah[4][4];
        #pragma unroll
        for (int mt = 0; mt < 4; mt++)
            LDSM4(ah[mt], sb + tile_off(s, 0, wm + mt * 16 + a_row, a_ch));
        uint32_t b4h[2][4], b4l[2][4];
        #pragma unroll
        for (int p = 0; p < 2; p++) {
            LDSM4(b4h[p], sb + tile_off(s, 1, wn + p * 16 + a_row, a_ch));
            LDSM4(b4l[p], sb + tile_off(s, 2, wn + p * 16 + a_row, a_ch));
        }
        uint32_t bh[4][2], bl[4][2];
        #pragma unroll
        for (int p = 0; p < 2; p++) {
            bh[2*p][0]   = b4h[p][0]; bh[2*p][1]   = b4h[p][2];
            bh[2*p+1][0] = b4h[p][1]; bh[2*p+1][1] = b4h[p][3];
            bl[2*p][0]   = b4l[p][0]; bl[2*p][1]   = b4l[p][2];
            bl[2*p+1][0] = b4l[p][1]; bl[2*p+1][1] = b4l[p][3];
        }
        #pragma unroll
        for (int mt = 0; mt < 4; mt++)
            #pragma unroll
            for (int nt = 0; nt < 4; nt++) {
                MMA16816H(acc[mt][nt], ah[mt], bh[nt]);
                MMA16816H(acc[mt][nt], ah[mt], bl[nt]);
            }
    }

    const int er = lane >> 2;
    const int ec = (lane & 3) * 2;
    #pragma unroll
    for (int mt = 0; mt < 4; mt++) {
        #pragma unroll
        for (int half = 0; half < 2; half++) {
            int m = m0 + wm + mt * 16 + er + half * 8;
            #pragma unroll
            for (int nt = 0; nt < 4; nt++) {
                int n = n0 + wn + nt * 8 + ec;
                float f0 = (acc[mt][nt][half * 2 + 0] + __ldg(&bias[n]))     * scale;
                float f1 = (acc[mt][nt][half * 2 + 1] + __ldg(&bias[n + 1])) * scale;
                if (LAYOUT == 0) {
                    *(u64*)&C[(size_t)m * DMODEL + n] = pack2(f0, f1);
                } else {
                    int b  = m >> 11;
                    int sq = m & (SS - 1);
                    int hh = n >> 6;
                    int dk = n & (DK - 1);
                    size_t o = ((((size_t)b * H + hh) * SS + sq) * DK) + dk;
                    uint32_t hi, lo;
                    split_pair(f0, f1, hi, lo);
                    *(uint32_t*)&Chi[o] = hi;
                    *(uint32_t*)&Clo[o] = lo;
                }
            }
        }
    }
}

__global__ __launch_bounds__(256, 2)
void gemm_qkv(const float* __restrict__ bq, const float* __restrict__ bk,
              const float* __restrict__ bv)
{
    __shared__ __align__(16) __half sm[NST * 3 * 128 * 16];   // 48KB
    const size_t z = blockIdx.z;
    const float* bias = (z == 0) ? bq : (z == 1) ? bk : bv;
    const float scale = (z == 0) ? QSCALE : 1.0f;
    gemm_body<1>(g_act + z * ACT_SZ,
                 g_wh + z * W_SZ, g_wl + z * W_SZ,
                 bias, nullptr,
                 g_headh + z * HEAD_SZ, g_headl + z * HEAD_SZ,
                 scale, sm);
}

__global__ __launch_bounds__(256, 2)
void gemm_out(const float* __restrict__ bo, float* __restrict__ C)
{
    __shared__ __align__(16) __half sm[NST * 3 * 128 * 16];   // 48KB
    gemm_body<0>(g_act, g_wh + 3 * W_SZ, g_wl + 3 * W_SZ,
                 bo, C, nullptr, nullptr, 1.0f, sm);
}

// ---------------------------------------------------------------------------
// HMMA flash attention (bf16x3) — R13 body (best-known). Epilogue writes
// fp16 activation (single array) for the O-projection.
// ---------------------------------------------------------------------------
__device__ __forceinline__ uint32_t kv_off(int s, int t, int row, int ch) {
    return (uint32_t)((((s * 4 + t) * 32 + row) * 128) + ((ch ^ (row & 7)) * 16));
}

__global__ __launch_bounds__(128)
void attn_mma()
{
    __shared__ __align__(16) char sKV[32768];   // 2 stages x 4 tiles x 4KB

    const int tid  = threadIdx.x;
    const int lane = tid & 31;
    const int w    = tid >> 5;
    const int wq   = w * 16;
    const int q0 = blockIdx.x * 64;
    const int h  = blockIdx.y;
    const int bz = blockIdx.z;
    const uint32_t sb = smem_u32(sKV);

    const size_t hb = ((size_t)bz * H + h) * SS;
    const __nv_bfloat16* gqh = g_headh + (hb + q0) * DK;
    const __nv_bfloat16* gql = g_headl + (hb + q0) * DK;
    const __nv_bfloat16* kvsrc[4] = {
        g_headh + HEAD_SZ + hb * DK, g_headl + HEAD_SZ + hb * DK,
        g_headh + 2 * HEAD_SZ + hb * DK, g_headl + 2 * HEAD_SZ + hb * DK };

    #pragma unroll
    for (int i = 0; i < 8; i++) {
        int idx = tid + i * 128;
        int arr = idx >> 9;
        int rem = idx & 511;
        int row = rem >> 3, ch = rem & 7;
        const __nv_bfloat16* src = (arr ? gql : gqh) + (size_t)row * DK + ch * 8;
        *(uint4*)(sKV + kv_off(0, arr * 2 + (row >> 5), row & 31, ch)) = *(const uint4*)src;
    }
    __syncthreads();

    uint32_t qfh[4][4], qfl[4][4];
    {
        const int a_row = lane & 15, a_ch = lane >> 4;
        const int r = wq + a_row, lr = r & 31, ts = r >> 5;
        #pragma unroll
        for (int ks = 0; ks < 4; ks++) {
            LDSM4(qfh[ks], sb + kv_off(0, ts, lr, ks * 2 + a_ch));
            LDSM4(qfl[ks], sb + kv_off(0, 2 + ts, lr, ks * 2 + a_ch));
        }
    }
    __syncthreads();

    float acc[8][4];
    #pragma unroll
    for (int nt = 0; nt < 8; nt++)
        #pragma unroll
        for (int e = 0; e < 4; e++) acc[nt][e] = 0.f;
    float mrun0 = -1e30f, mrun1 = -1e30f;
    float lp0 = 0.f, lp1 = 0.f;

    const int er = lane >> 2, ec = (lane & 3) * 2;
    const size_t mrow0 = ((size_t)bz * SS + q0 + wq + er) * (SS / 32);
    const size_t mrow1 = mrow0 + 8 * (SS / 32);

    #pragma unroll
    for (int i = 0; i < 8; i++) {
        int idx = tid + i * 128;
        int t = idx >> 8, rem = idx & 255, row = rem >> 3, ch = rem & 7;
        CP_ASYNC16(sb + kv_off(0, t, row, ch), kvsrc[t] + (size_t)row * DK + ch * 8);
    }
    CP_COMMIT();

    for (int it = 0; it < SS / 32; it++) {
        const int st = it & 1;
        CP_WAIT(0);
        __syncthreads();

        if (it + 1 < SS / 32) {
            const int k0n = (it + 1) * 32;
            #pragma unroll
            for (int i = 0; i < 8; i++) {
                int idx = tid + i * 128;
                int t = idx >> 8, rem = idx & 255, row = rem >> 3, ch = rem & 7;
                CP_ASYNC16(sb + kv_off(st ^ 1, t, row, ch),
                           kvsrc[t] + (size_t)(k0n + row) * DK + ch * 8);
            }
        }
        CP_COMMIT();

        float sc[4][4];
        #pragma unroll
        for (int nt = 0; nt < 4; nt++)
            #pragma unroll
            for (int e = 0; e < 4; e++) sc[nt][e] = 0.f;

        #pragma unroll
        for (int ks = 0; ks < 4; ks++) {
            uint32_t kc0h[4], kc1h[4], kc0l[4], kc1l[4];
            LDSM4(kc0h, sb + kv_off(st, 0, lane, ks * 2));
            LDSM4(kc1h, sb + kv_off(st, 0, lane, ks * 2 + 1));
            LDSM4(kc0l, sb + kv_off(st, 1, lane, ks * 2));
            LDSM4(kc1l, sb + kv_off(st, 1, lane, ks * 2 + 1));
            #pragma unroll
            for (int nt = 0; nt < 4; nt++) {
                uint32_t bh[2] = { kc0h[nt], kc1h[nt] };
                uint32_t bl[2] = { kc0l[nt], kc1l[nt] };
                MMA16816(sc[nt], qfh[ks], bh);
                MMA16816(sc[nt], qfh[ks], bl);
                MMA16816(sc[nt], qfl[ks], bh);
            }
        }

        unsigned mw0 = g_mbits[mrow0 + it];
        unsigned mw1 = g_mbits[mrow1 + it];
        #pragma unroll
        for (int nt = 0; nt < 4; nt++) {
            int j0 = nt * 8 + ec;
            if (!((mw0 >> j0) & 1u))       sc[nt][0] = MASKVAL;
            if (!((mw0 >> (j0 + 1)) & 1u)) sc[nt][1] = MASKVAL;
            if (!((mw1 >> j0) & 1u))       sc[nt][2] = MASKVAL;
            if (!((mw1 >> (j0 + 1)) & 1u)) sc[nt][3] = MASKVAL;
        }
        float m0 = mrun0, m1 = mrun1;
        #pragma unroll
        for (int nt = 0; nt < 4; nt++) {
            m0 = fmaxf(m0, fmaxf(sc[nt][0], sc[nt][1]));
            m1 = fmaxf(m1, fmaxf(sc[nt][2], sc[nt][3]));
        }
        m0 = fmaxf(m0, __shfl_xor_sync(0xffffffff, m0, 1));
        m0 = fmaxf(m0, __shfl_xor_sync(0xffffffff, m0, 2));
        m1 = fmaxf(m1, __shfl_xor_sync(0xffffffff, m1, 1));
        m1 = fmaxf(m1, __shfl_xor_sync(0xffffffff, m1, 2));
        float al0 = ex2(mrun0 - m0);
        float al1 = ex2(mrun1 - m1);
        mrun0 = m0; mrun1 = m1;
        lp0 *= al0; lp1 *= al1;
        #pragma unroll
        for (int nt = 0; nt < 8; nt++) {
            acc[nt][0] *= al0; acc[nt][1] *= al0;
            acc[nt][2] *= al1; acc[nt][3] *= al1;
        }
        float s0 = 0.f, s1 = 0.f;
        #pragma unroll
        for (int nt = 0; nt < 4; nt++) {
            sc[nt][0] = ex2(sc[nt][0] - m0); s0 += sc[nt][0];
            sc[nt][1] = ex2(sc[nt][1] - m0); s0 += sc[nt][1];
            sc[nt][2] = ex2(sc[nt][2] - m1); s1 += sc[nt][2];
            sc[nt][3] = ex2(sc[nt][3] - m1); s1 += sc[nt][3];
        }
        lp0 += s0; lp1 += s1;

        #pragma unroll
        for (int t2 = 0; t2 < 2; t2++) {
            uint32_t ph[4], pl[4];
            split_pair(sc[2*t2][0],   sc[2*t2][1],   ph[0], pl[0]);
            split_pair(sc[2*t2][2],   sc[2*t2][3],   ph[1], pl[1]);
            split_pair(sc[2*t2+1][0], sc[2*t2+1][1], ph[2], pl[2]);
            split_pair(sc[2*t2+1][2], sc[2*t2+1][3], ph[3], pl[3]);
            const int vrow = t2 * 16 + (lane & 15);
            const int vch  = lane >> 4;
            #pragma unroll
            for (int p = 0; p < 4; p++) {
                uint32_t v4h[4], v4l[4];
                LDSM4T(v4h, sb + kv_off(st, 2, vrow, 2 * p + vch));
                LDSM4T(v4l, sb + kv_off(st, 3, vrow, 2 * p + vch));
                uint32_t vh0[2] = { v4h[0], v4h[1] }, vl0[2] = { v4l[0], v4l[1] };
                uint32_t vh1[2] = { v4h[2], v4h[3] }, vl1[2] = { v4l[2], v4l[3] };
                MMA16816(acc[2*p],   ph, vh0);
                MMA16816(acc[2*p],   ph, vl0);
                MMA16816(acc[2*p],   pl, vh0);
                MMA16816(acc[2*p+1], ph, vh1);
                MMA16816(acc[2*p+1], ph, vl1);
                MMA16816(acc[2*p+1], pl, vh1);
            }
        }
    }

    lp0 += __shfl_xor_sync(0xffffffff, lp0, 1);
    lp0 += __shfl_xor_sync(0xffffffff, lp0, 2);
    lp1 += __shfl_xor_sync(0xffffffff, lp1, 1);
    lp1 += __shfl_xor_sync(0xffffffff, lp1, 2);
    float inv0 = 1.0f / lp0;
    float inv1 = 1.0f / lp1;

    size_t ro0 = ((size_t)bz * SS + q0 + wq + er) * DMODEL + (size_t)h * DK;
    size_t ro1 = ro0 + 8 * DMODEL;
    #pragma unroll
    for (int nt = 0; nt < 8; nt++) {
        int c = nt * 8 + ec;
        __half2 o0 = __floats2half2_rn(acc[nt][0] * inv0, acc[nt][1] * inv0);
        __half2 o1 = __floats2half2_rn(acc[nt][2] * inv1, acc[nt][3] * inv1);
        *(uint32_t*)&g_act[ro0 + c] = *(uint32_t*)&o0;
        *(uint32_t*)&g_act[ro1 + c] = *(uint32_t*)&o1;
    }
}

// ---------------------------------------------------------------------------
extern "C" void kernel_launch(void* const* d_in, const int* in_sizes, int n_in,
                              void* d_out, int out_size)
{
    const float* q    = (const float*)d_in[0];
    const float* k    = (const float*)d_in[1];
    const float* v    = (const float*)d_in[2];
    const int*   mask = (const int*)  d_in[3];
    const float* Wq   = (const float*)d_in[4];
    const float* bq   = (const float*)d_in[5];
    const float* Wk   = (const float*)d_in[6];
    const float* bk   = (const float*)d_in[7];
    const float* Wv   = (const float*)d_in[8];
    const float* bv   = (const float*)d_in[9];
    const float* Wo   = (const float*)d_in[10];
    const float* bo   = (const float*)d_in[11];
    float* out = (float*)d_out;

    const int ACT_BLKS = (M_ROWS * DMODEL) / (256 * 4);   // 4096
    const int W_BLKS   = (DMODEL * DMODEL) / (256 * 4);   // 1024
    dim3 gq3(DMODEL / 128, M_ROWS / 128, 3);               // (8, 32, 3)
    dim3 go(DMODEL / 128, M_ROWS / 128);                   // (8, 32)

    pack_mask<<<(size_t)BB * SS * SS / 256, 256>>>(mask);
    conv_split_w<<<dim3(W_BLKS, 4), 256>>>(Wq, Wk, Wv, Wo);
    conv_act<<<dim3(ACT_BLKS, 3), 256>>>(q, k, v);

    gemm_qkv<<<gq3, 256>>>(bq, bk, bv);

    attn_mma<<<dim3(SS / 64, H, BB), 128>>>();

    gemm_out<<<go, 256>>>(bo, out);
}